// round 1
// baseline (speedup 1.0000x reference)
#include <cuda_runtime.h>
#include <math.h>

#define B_  8
#define S_  256
#define H_  768
#define L_  12
#define NH_ 12
#define D_  64
#define FF_ 3072
#define NL_ 9
#define M_  (B_*S_)   // 2048 token rows

// ---------------- scratch (device globals: allowed, no allocations) ---------
__device__ float g_h  [M_*H_];
__device__ float g_q  [M_*H_];
__device__ float g_k  [M_*H_];
__device__ float g_v  [M_*H_];
__device__ float g_ctx[M_*H_];
__device__ float g_tmp[M_*H_];
__device__ float g_ff [M_*FF_];
__device__ float g_cmp[M_*H_];
__device__ float g_bias[M_];
__device__ int   g_order[M_];

// ---------------- embeddings + LayerNorm ------------------------------------
__global__ __launch_bounds__(256) void embed_kernel(
    const int* __restrict__ ids, const int* __restrict__ types,
    const float* __restrict__ we, const float* __restrict__ pe,
    const float* __restrict__ te,
    const float* __restrict__ g, const float* __restrict__ bta)
{
    int row = blockIdx.x;           // 0..2047
    int s   = row % S_;
    int t   = threadIdx.x;
    __shared__ float x[H_];
    __shared__ float red[256];

    int id = ids[row];
    int ty = types[row];
    for (int e = t; e < H_; e += 256)
        x[e] = we[id*H_ + e] + pe[s*H_ + e] + te[ty*H_ + e];
    __syncthreads();

    float lsum = 0.f;
    for (int e = t; e < H_; e += 256) lsum += x[e];
    red[t] = lsum; __syncthreads();
    for (int st = 128; st > 0; st >>= 1) { if (t < st) red[t] += red[t+st]; __syncthreads(); }
    float mean = red[0] * (1.0f / H_);
    __syncthreads();

    float lv = 0.f;
    for (int e = t; e < H_; e += 256) { float d = x[e] - mean; lv += d*d; }
    red[t] = lv; __syncthreads();
    for (int st = 128; st > 0; st >>= 1) { if (t < st) red[t] += red[t+st]; __syncthreads(); }
    float rstd = rsqrtf(red[0] * (1.0f / H_) + 1e-12f);

    for (int e = t; e < H_; e += 256)
        g_h[row*H_ + e] = (x[e] - mean) * rstd * g[e] + bta[e];
}

// ---------------- generic LayerNorm (tmp -> h) -------------------------------
__global__ __launch_bounds__(256) void ln_kernel(
    const float* __restrict__ in, const float* __restrict__ g,
    const float* __restrict__ bta, float* __restrict__ outp)
{
    int row = blockIdx.x;
    int t   = threadIdx.x;
    __shared__ float red[256];
    const float* xr = in + row*H_;

    float lsum = 0.f;
    for (int e = t; e < H_; e += 256) lsum += xr[e];
    red[t] = lsum; __syncthreads();
    for (int st = 128; st > 0; st >>= 1) { if (t < st) red[t] += red[t+st]; __syncthreads(); }
    float mean = red[0] * (1.0f / H_);
    __syncthreads();

    float lv = 0.f;
    for (int e = t; e < H_; e += 256) { float d = xr[e] - mean; lv += d*d; }
    red[t] = lv; __syncthreads();
    for (int st = 128; st > 0; st >>= 1) { if (t < st) red[t] += red[t+st]; __syncthreads(); }
    float rstd = rsqrtf(red[0] * (1.0f / H_) + 1e-12f);

    for (int e = t; e < H_; e += 256)
        outp[row*H_ + e] = (xr[e] - mean) * rstd * g[e] + bta[e];
}

// ---------------- attention mask bias ----------------------------------------
__global__ void bias_kernel(const int* __restrict__ mask)
{
    int i = blockIdx.x * 256 + threadIdx.x;
    if (i < M_) g_bias[i] = (1.0f - (float)mask[i]) * -1e4f;
}

// ---------------- tiled SGEMM: C = A(MxK) @ B(KxN) + bias (+res) (+gelu) ----
#define BM 64
#define BN 64
#define BK 16
__global__ __launch_bounds__(256) void gemm_kernel(
    const float* __restrict__ A, const float* __restrict__ B,
    const float* __restrict__ bias, const float* __restrict__ res,
    float* __restrict__ C, int M, int N, int K, int act)
{
    __shared__ float As[BK][BM + 1];
    __shared__ float Bs[BK][BN];

    const int tid  = threadIdx.x;
    const int row0 = blockIdx.y * BM;
    const int col0 = blockIdx.x * BN;
    const int tr   = tid >> 4;           // 0..15
    const int tc   = tid & 15;           // 0..15

    const int arow = tid >> 2;           // 0..63
    const int acol = (tid & 3) << 2;     // 0,4,8,12
    const int brow = tid >> 4;           // 0..15
    const int bcol = (tid & 15) << 2;    // 0..60

    float acc[4][4];
    #pragma unroll
    for (int i = 0; i < 4; i++)
        #pragma unroll
        for (int j = 0; j < 4; j++) acc[i][j] = 0.f;

    for (int k0 = 0; k0 < K; k0 += BK) {
        float4 a4 = *reinterpret_cast<const float4*>(&A[(row0 + arow)*K + k0 + acol]);
        As[acol + 0][arow] = a4.x;
        As[acol + 1][arow] = a4.y;
        As[acol + 2][arow] = a4.z;
        As[acol + 3][arow] = a4.w;
        float4 b4 = *reinterpret_cast<const float4*>(&B[(k0 + brow)*N + col0 + bcol]);
        *reinterpret_cast<float4*>(&Bs[brow][bcol]) = b4;
        __syncthreads();

        #pragma unroll
        for (int k = 0; k < BK; k++) {
            float av[4], bv[4];
            #pragma unroll
            for (int i = 0; i < 4; i++) av[i] = As[k][tr*4 + i];
            #pragma unroll
            for (int j = 0; j < 4; j++) bv[j] = Bs[k][tc*4 + j];
            #pragma unroll
            for (int i = 0; i < 4; i++)
                #pragma unroll
                for (int j = 0; j < 4; j++)
                    acc[i][j] = fmaf(av[i], bv[j], acc[i][j]);
        }
        __syncthreads();
    }

    #pragma unroll
    for (int i = 0; i < 4; i++) {
        int r = row0 + tr*4 + i;
        #pragma unroll
        for (int j = 0; j < 4; j++) {
            int c = col0 + tc*4 + j;
            float v = acc[i][j] + bias[c];
            if (res) v += res[r*N + c];
            if (act) v = 0.5f * v * (1.0f + erff(v * 0.70710678118654752f));
            C[r*N + c] = v;
        }
    }
}

// ---------------- fused attention: one block per (q-row, head, batch) -------
__global__ __launch_bounds__(256) void attn_kernel()
{
    int qi = blockIdx.x, h = blockIdx.y, b = blockIdx.z;
    int t  = threadIdx.x;
    __shared__ float qrow[D_];
    __shared__ float sc[S_];
    __shared__ float red[256];
    __shared__ float part[4][D_];

    const float* qp = g_q + (b*S_ + qi)*H_ + h*D_;
    if (t < D_) qrow[t] = qp[t];
    __syncthreads();

    // scores: thread t handles key t
    const float* kp = g_k + (b*S_ + t)*H_ + h*D_;
    float s = 0.f;
    #pragma unroll
    for (int d = 0; d < D_; d++) s = fmaf(qrow[d], kp[d], s);
    s = s * 0.125f + g_bias[b*S_ + t];

    // softmax (max)
    red[t] = s; __syncthreads();
    for (int st = 128; st > 0; st >>= 1) { if (t < st) red[t] = fmaxf(red[t], red[t+st]); __syncthreads(); }
    float mx = red[0]; __syncthreads();
    float e = __expf(s - mx);
    sc[t] = e; red[t] = e; __syncthreads();
    for (int st = 128; st > 0; st >>= 1) { if (t < st) red[t] += red[t+st]; __syncthreads(); }
    float inv = 1.0f / red[0];
    __syncthreads();

    // ctx: 4 partial groups of 64 keys, 64 dims each (coalesced v loads)
    int d = t & (D_ - 1), p = t >> 6;
    const float* vp = g_v + (b*S_ + p*64)*H_ + h*D_ + d;
    float acc = 0.f;
    #pragma unroll 8
    for (int tt = 0; tt < 64; tt++) acc = fmaf(sc[p*64 + tt], vp[tt*H_], acc);
    part[p][d] = acc;
    __syncthreads();
    if (t < D_)
        g_ctx[(b*S_ + qi)*H_ + h*D_ + t] =
            (part[0][t] + part[1][t] + part[2][t] + part[3][t]) * inv;
}

// ---------------- stable compaction order per batch --------------------------
__global__ __launch_bounds__(256) void order_kernel(const int* __restrict__ valid)
{
    int b = blockIdx.x, t = threadIdx.x;
    __shared__ int sc[256];
    __shared__ int ord[256];
    int v = valid[b*S_ + t];
    sc[t] = v; __syncthreads();
    for (int off = 1; off < 256; off <<= 1) {
        int x = (t >= off) ? sc[t - off] : 0;
        __syncthreads();
        sc[t] += x;
        __syncthreads();
    }
    ord[t] = -1; __syncthreads();
    if (v) ord[sc[t] - v] = t;      // exclusive prefix = inclusive - v
    __syncthreads();
    g_order[b*S_ + t] = ord[t];
}

__global__ __launch_bounds__(256) void compact_kernel()
{
    int row = blockIdx.x;
    int b = row / S_;
    int src = g_order[row];
    int t = threadIdx.x;
    if (src < 0) {
        for (int e = t; e < H_; e += 256) g_cmp[row*H_ + e] = 0.f;
    } else {
        const float* xp = g_h + (b*S_ + src)*H_;
        for (int e = t; e < H_; e += 256) g_cmp[row*H_ + e] = xp[e];
    }
}

// ---------------- classifier + softmax ---------------------------------------
__global__ __launch_bounds__(256) void clf_kernel(
    const float* __restrict__ W, const float* __restrict__ bias,
    float* __restrict__ outp)
{
    int row = blockIdx.x, t = threadIdx.x;
    __shared__ float red[256][NL_ + 1];
    float p[NL_];
    #pragma unroll
    for (int c = 0; c < NL_; c++) p[c] = 0.f;
    for (int e = t; e < H_; e += 256) {
        float x = g_cmp[row*H_ + e];
        #pragma unroll
        for (int c = 0; c < NL_; c++) p[c] = fmaf(x, W[e*NL_ + c], p[c]);
    }
    #pragma unroll
    for (int c = 0; c < NL_; c++) red[t][c] = p[c];
    __syncthreads();
    for (int st = 128; st > 0; st >>= 1) {
        if (t < st)
            #pragma unroll
            for (int c = 0; c < NL_; c++) red[t][c] += red[t+st][c];
        __syncthreads();
    }
    if (t == 0) {
        float l[NL_], mx = -1e30f, sum = 0.f;
        #pragma unroll
        for (int c = 0; c < NL_; c++) { l[c] = red[0][c] + bias[c]; mx = fmaxf(mx, l[c]); }
        #pragma unroll
        for (int c = 0; c < NL_; c++) { l[c] = expf(l[c] - mx); sum += l[c]; }
        float inv = 1.0f / sum;
        #pragma unroll
        for (int c = 0; c < NL_; c++) outp[row*NL_ + c] = l[c] * inv;
    }
}

// ---------------- launch --------------------------------------------------
extern "C" void kernel_launch(void* const* d_in, const int* in_sizes, int n_in,
                              void* d_out, int out_size)
{
    const int*   ids   = (const int*)  d_in[0];
    const int*   mask  = (const int*)  d_in[1];
    const int*   types = (const int*)  d_in[2];
    const int*   valid = (const int*)  d_in[3];
    const float* we    = (const float*)d_in[4];
    const float* pe    = (const float*)d_in[5];
    const float* te    = (const float*)d_in[6];
    const float* elg   = (const float*)d_in[7];
    const float* elb   = (const float*)d_in[8];
    const float* Wq    = (const float*)d_in[9];
    const float* bq    = (const float*)d_in[10];
    const float* Wk    = (const float*)d_in[11];
    const float* bk    = (const float*)d_in[12];
    const float* Wv    = (const float*)d_in[13];
    const float* bv    = (const float*)d_in[14];
    const float* Wo    = (const float*)d_in[15];
    const float* bo    = (const float*)d_in[16];
    const float* l1g   = (const float*)d_in[17];
    const float* l1b   = (const float*)d_in[18];
    const float* Wi    = (const float*)d_in[19];
    const float* bi    = (const float*)d_in[20];
    const float* Wo2   = (const float*)d_in[21];
    const float* bo2   = (const float*)d_in[22];
    const float* l2g   = (const float*)d_in[23];
    const float* l2b   = (const float*)d_in[24];
    const float* cW    = (const float*)d_in[25];
    const float* cb    = (const float*)d_in[26];
    float* outp = (float*)d_out;

    float *ph, *pq, *pk, *pv, *pctx, *ptmp, *pff;
    cudaGetSymbolAddress((void**)&ph,   g_h);
    cudaGetSymbolAddress((void**)&pq,   g_q);
    cudaGetSymbolAddress((void**)&pk,   g_k);
    cudaGetSymbolAddress((void**)&pv,   g_v);
    cudaGetSymbolAddress((void**)&pctx, g_ctx);
    cudaGetSymbolAddress((void**)&ptmp, g_tmp);
    cudaGetSymbolAddress((void**)&pff,  g_ff);

    embed_kernel<<<M_, 256>>>(ids, types, we, pe, te, elg, elb);
    bias_kernel<<<(M_ + 255)/256, 256>>>(mask);

    dim3 gH (H_ / BN, M_ / BM);   // (12, 32)
    dim3 gFF(FF_ / BN, M_ / BM);  // (48, 32)

    for (int l = 0; l < L_; l++) {
        const float* wq = Wq + (size_t)l*H_*H_;
        const float* wk = Wk + (size_t)l*H_*H_;
        const float* wv = Wv + (size_t)l*H_*H_;
        const float* wo = Wo + (size_t)l*H_*H_;
        const float* wi = Wi + (size_t)l*H_*FF_;
        const float* w2 = Wo2 + (size_t)l*FF_*H_;

        gemm_kernel<<<gH, 256>>>(ph, wq, bq + l*H_, nullptr, pq, M_, H_, H_, 0);
        gemm_kernel<<<gH, 256>>>(ph, wk, bk + l*H_, nullptr, pk, M_, H_, H_, 0);
        gemm_kernel<<<gH, 256>>>(ph, wv, bv + l*H_, nullptr, pv, M_, H_, H_, 0);

        attn_kernel<<<dim3(S_, NH_, B_), 256>>>();

        gemm_kernel<<<gH, 256>>>(pctx, wo, bo + l*H_, ph, ptmp, M_, H_, H_, 0);
        ln_kernel<<<M_, 256>>>(ptmp, l1g + l*H_, l1b + l*H_, ph);

        gemm_kernel<<<gFF, 256>>>(ph, wi, bi + l*FF_, nullptr, pff, M_, FF_, H_, 1);
        gemm_kernel<<<gH, 256>>>(pff, w2, bo2 + l*H_, ph, ptmp, M_, H_, FF_, 0);
        ln_kernel<<<M_, 256>>>(ptmp, l2g + l*H_, l2b + l*H_, ph);
    }

    order_kernel<<<B_, 256>>>(valid);
    compact_kernel<<<M_, 256>>>();
    clf_kernel<<<M_, 256>>>(cW, cb, outp);
}

// round 2
// speedup vs baseline: 2.7238x; 2.7238x over previous
#include <cuda_runtime.h>
#include <math.h>

#define B_  8
#define S_  256
#define H_  768
#define L_  12
#define NH_ 12
#define D_  64
#define FF_ 3072
#define NL_ 9
#define M_  (B_*S_)   // 2048 token rows

// ---------------- scratch (device globals: allowed, no allocations) ---------
__device__ float g_h  [M_*H_];
__device__ float g_q  [M_*H_];
__device__ float g_k  [M_*H_];
__device__ float g_v  [M_*H_];
__device__ float g_ctx[M_*H_];
__device__ float g_tmp[M_*H_];
__device__ float g_ff [M_*FF_];
__device__ float g_cmp[M_*H_];
__device__ float g_bias[M_];
__device__ int   g_order[M_];

// ---------------- tf32 helper ------------------------------------------------
__device__ __forceinline__ unsigned f2tf(float x) {
    unsigned r;
    asm("cvt.rna.tf32.f32 %0, %1;" : "=r"(r) : "f"(x));
    return r;
}

// ---------------- embeddings + LayerNorm ------------------------------------
__global__ __launch_bounds__(256) void embed_kernel(
    const int* __restrict__ ids, const int* __restrict__ types,
    const float* __restrict__ we, const float* __restrict__ pe,
    const float* __restrict__ te,
    const float* __restrict__ g, const float* __restrict__ bta)
{
    int row = blockIdx.x;
    int s   = row % S_;
    int t   = threadIdx.x;
    __shared__ float x[H_];
    __shared__ float red[256];

    int id = ids[row];
    int ty = types[row];
    for (int e = t; e < H_; e += 256)
        x[e] = we[id*H_ + e] + pe[s*H_ + e] + te[ty*H_ + e];
    __syncthreads();

    float lsum = 0.f;
    for (int e = t; e < H_; e += 256) lsum += x[e];
    red[t] = lsum; __syncthreads();
    for (int st = 128; st > 0; st >>= 1) { if (t < st) red[t] += red[t+st]; __syncthreads(); }
    float mean = red[0] * (1.0f / H_);
    __syncthreads();

    float lv = 0.f;
    for (int e = t; e < H_; e += 256) { float d = x[e] - mean; lv += d*d; }
    red[t] = lv; __syncthreads();
    for (int st = 128; st > 0; st >>= 1) { if (t < st) red[t] += red[t+st]; __syncthreads(); }
    float rstd = rsqrtf(red[0] * (1.0f / H_) + 1e-12f);

    for (int e = t; e < H_; e += 256)
        g_h[row*H_ + e] = (x[e] - mean) * rstd * g[e] + bta[e];
}

// ---------------- generic LayerNorm ------------------------------------------
__global__ __launch_bounds__(256) void ln_kernel(
    const float* __restrict__ in, const float* __restrict__ g,
    const float* __restrict__ bta, float* __restrict__ outp)
{
    int row = blockIdx.x;
    int t   = threadIdx.x;
    __shared__ float red[256];
    const float* xr = in + row*H_;

    float lsum = 0.f;
    for (int e = t; e < H_; e += 256) lsum += xr[e];
    red[t] = lsum; __syncthreads();
    for (int st = 128; st > 0; st >>= 1) { if (t < st) red[t] += red[t+st]; __syncthreads(); }
    float mean = red[0] * (1.0f / H_);
    __syncthreads();

    float lv = 0.f;
    for (int e = t; e < H_; e += 256) { float d = xr[e] - mean; lv += d*d; }
    red[t] = lv; __syncthreads();
    for (int st = 128; st > 0; st >>= 1) { if (t < st) red[t] += red[t+st]; __syncthreads(); }
    float rstd = rsqrtf(red[0] * (1.0f / H_) + 1e-12f);

    for (int e = t; e < H_; e += 256)
        outp[row*H_ + e] = (xr[e] - mean) * rstd * g[e] + bta[e];
}

// ---------------- attention mask bias ----------------------------------------
__global__ void bias_kernel(const int* __restrict__ mask)
{
    int i = blockIdx.x * 256 + threadIdx.x;
    if (i < M_) g_bias[i] = (1.0f - (float)mask[i]) * -1e4f;
}

// ---------------- tf32 tensor-core GEMM ---------------------------------------
// C = A(MxK) @ B(KxN) + bias (+res) (+gelu).  BM=64, BN=128, BK=16, 256 threads.
// grid.z selects among up to 3 (W, bias, C) triples (QKV fusion).
#define GBM 64
#define GBN 128
#define GBK 16

__global__ __launch_bounds__(256, 2) void gemm_mma(
    const float* __restrict__ A,
    const float* __restrict__ W0, const float* __restrict__ W1, const float* __restrict__ W2,
    const float* __restrict__ bi0, const float* __restrict__ bi1, const float* __restrict__ bi2,
    float* __restrict__ C0, float* __restrict__ C1, float* __restrict__ C2,
    const float* __restrict__ res, int M, int N, int K, int act)
{
    const float* B    = (blockIdx.z == 0) ? W0 : (blockIdx.z == 1 ? W1 : W2);
    const float* bias = (blockIdx.z == 0) ? bi0 : (blockIdx.z == 1 ? bi1 : bi2);
    float*       C    = (blockIdx.z == 0) ? C0 : (blockIdx.z == 1 ? C1 : C2);

    __shared__ unsigned As[GBM][20];    // stride 20 -> conflict-free frag reads
    __shared__ unsigned Bs[GBK][136];   // stride 136 -> conflict-free frag reads

    const int tid  = threadIdx.x;
    const int row0 = blockIdx.y * GBM;
    const int col0 = blockIdx.x * GBN;

    // loaders
    const int ar = tid >> 2,  ac = (tid & 3) << 2;   // A: 64 rows x 16 cols, one float4/thread
    const int br = tid >> 5,  bc = (tid & 31) << 2;  // B: rows br, br+8; 128 cols, two float4/thread

    // compute mapping
    const int warp = tid >> 5, lane = tid & 31;
    const int wm = warp >> 2, wn = warp & 3;         // 2 x 4 warp grid
    const int grp = lane >> 2, tg = lane & 3;

    float acc[2][4][4];
    #pragma unroll
    for (int i = 0; i < 2; i++)
        #pragma unroll
        for (int j = 0; j < 4; j++)
            #pragma unroll
            for (int c = 0; c < 4; c++) acc[i][j][c] = 0.f;

    const float* Abase = A + (size_t)(row0 + ar)*K + ac;
    const float* Bbase = B + (size_t)br*N + col0 + bc;

    float4 ra  = *(const float4*)(Abase);
    float4 rb0 = *(const float4*)(Bbase);
    float4 rb1 = *(const float4*)(Bbase + 8*(size_t)N);

    for (int kk = 0; kk < K; kk += GBK) {
        // stage to smem (with tf32 rounding)
        *(uint4*)&As[ar][ac] = make_uint4(f2tf(ra.x), f2tf(ra.y), f2tf(ra.z), f2tf(ra.w));
        *(uint4*)&Bs[br][bc] = make_uint4(f2tf(rb0.x), f2tf(rb0.y), f2tf(rb0.z), f2tf(rb0.w));
        *(uint4*)&Bs[br+8][bc] = make_uint4(f2tf(rb1.x), f2tf(rb1.y), f2tf(rb1.z), f2tf(rb1.w));
        __syncthreads();

        if (kk + GBK < K) {   // prefetch next tile into registers (overlaps compute)
            ra  = *(const float4*)(Abase + kk + GBK);
            rb0 = *(const float4*)(Bbase + (size_t)(kk + GBK)*N);
            rb1 = *(const float4*)(Bbase + (size_t)(kk + GBK + 8)*N);
        }

        #pragma unroll
        for (int k8 = 0; k8 < GBK; k8 += 8) {
            unsigned af[2][4], bf[4][2];
            #pragma unroll
            for (int mt = 0; mt < 2; mt++) {
                int r = wm*32 + mt*16 + grp;
                af[mt][0] = As[r][k8 + tg];
                af[mt][1] = As[r + 8][k8 + tg];
                af[mt][2] = As[r][k8 + tg + 4];
                af[mt][3] = As[r + 8][k8 + tg + 4];
            }
            #pragma unroll
            for (int nt = 0; nt < 4; nt++) {
                int c = wn*32 + nt*8 + grp;
                bf[nt][0] = Bs[k8 + tg][c];
                bf[nt][1] = Bs[k8 + tg + 4][c];
            }
            #pragma unroll
            for (int mt = 0; mt < 2; mt++)
                #pragma unroll
                for (int nt = 0; nt < 4; nt++) {
                    asm volatile(
                        "mma.sync.aligned.m16n8k8.row.col.f32.tf32.tf32.f32 "
                        "{%0,%1,%2,%3},{%4,%5,%6,%7},{%8,%9},{%0,%1,%2,%3};\n"
                        : "+f"(acc[mt][nt][0]), "+f"(acc[mt][nt][1]),
                          "+f"(acc[mt][nt][2]), "+f"(acc[mt][nt][3])
                        : "r"(af[mt][0]), "r"(af[mt][1]), "r"(af[mt][2]), "r"(af[mt][3]),
                          "r"(bf[nt][0]), "r"(bf[nt][1]));
                }
        }
        __syncthreads();
    }

    // epilogue
    #pragma unroll
    for (int mt = 0; mt < 2; mt++) {
        #pragma unroll
        for (int nt = 0; nt < 4; nt++) {
            int r0 = row0 + wm*32 + mt*16 + grp;
            int r1 = r0 + 8;
            int c  = col0 + wn*32 + nt*8 + 2*tg;
            float b0 = bias[c], b1 = bias[c+1];
            float v00 = acc[mt][nt][0] + b0, v01 = acc[mt][nt][1] + b1;
            float v10 = acc[mt][nt][2] + b0, v11 = acc[mt][nt][3] + b1;
            if (res) {
                v00 += res[(size_t)r0*N + c];     v01 += res[(size_t)r0*N + c + 1];
                v10 += res[(size_t)r1*N + c];     v11 += res[(size_t)r1*N + c + 1];
            }
            if (act) {
                v00 = 0.5f*v00*(1.0f + erff(v00*0.70710678118654752f));
                v01 = 0.5f*v01*(1.0f + erff(v01*0.70710678118654752f));
                v10 = 0.5f*v10*(1.0f + erff(v10*0.70710678118654752f));
                v11 = 0.5f*v11*(1.0f + erff(v11*0.70710678118654752f));
            }
            *(float2*)&C[(size_t)r0*N + c] = make_float2(v00, v01);
            *(float2*)&C[(size_t)r1*N + c] = make_float2(v10, v11);
        }
    }
}

// ---------------- fused attention: one block per (q-row, head, batch) -------
__global__ __launch_bounds__(256) void attn_kernel()
{
    int qi = blockIdx.x, h = blockIdx.y, b = blockIdx.z;
    int t  = threadIdx.x;
    __shared__ float4 qrow[D_/4];
    __shared__ float sc[S_];
    __shared__ float red[256];
    __shared__ float part[4][D_];

    const float* qp = g_q + (b*S_ + qi)*H_ + h*D_;
    if (t < D_/4) qrow[t] = ((const float4*)qp)[t];
    __syncthreads();

    // scores: thread t handles key t (vectorized dot)
    const float4* kp = (const float4*)(g_k + (b*S_ + t)*H_ + h*D_);
    float s = 0.f;
    #pragma unroll
    for (int d = 0; d < D_/4; d++) {
        float4 kv = kp[d];
        float4 qv = qrow[d];
        s = fmaf(qv.x, kv.x, s);
        s = fmaf(qv.y, kv.y, s);
        s = fmaf(qv.z, kv.z, s);
        s = fmaf(qv.w, kv.w, s);
    }
    s = s * 0.125f + g_bias[b*S_ + t];

    // softmax
    red[t] = s; __syncthreads();
    for (int st = 128; st > 0; st >>= 1) { if (t < st) red[t] = fmaxf(red[t], red[t+st]); __syncthreads(); }
    float mx = red[0]; __syncthreads();
    float e = __expf(s - mx);
    sc[t] = e; red[t] = e; __syncthreads();
    for (int st = 128; st > 0; st >>= 1) { if (t < st) red[t] += red[t+st]; __syncthreads(); }
    float inv = 1.0f / red[0];
    __syncthreads();

    // ctx
    int d = t & (D_ - 1), p = t >> 6;
    const float* vp = g_v + (b*S_ + p*64)*H_ + h*D_ + d;
    float acc = 0.f;
    #pragma unroll 8
    for (int tt = 0; tt < 64; tt++) acc = fmaf(sc[p*64 + tt], vp[tt*H_], acc);
    part[p][d] = acc;
    __syncthreads();
    if (t < D_)
        g_ctx[(b*S_ + qi)*H_ + h*D_ + t] =
            (part[0][t] + part[1][t] + part[2][t] + part[3][t]) * inv;
}

// ---------------- stable compaction order per batch --------------------------
__global__ __launch_bounds__(256) void order_kernel(const int* __restrict__ valid)
{
    int b = blockIdx.x, t = threadIdx.x;
    __shared__ int sc[256];
    __shared__ int ord[256];
    int v = valid[b*S_ + t];
    sc[t] = v; __syncthreads();
    for (int off = 1; off < 256; off <<= 1) {
        int x = (t >= off) ? sc[t - off] : 0;
        __syncthreads();
        sc[t] += x;
        __syncthreads();
    }
    ord[t] = -1; __syncthreads();
    if (v) ord[sc[t] - v] = t;
    __syncthreads();
    g_order[b*S_ + t] = ord[t];
}

__global__ __launch_bounds__(256) void compact_kernel()
{
    int row = blockIdx.x;
    int b = row / S_;
    int src = g_order[row];
    int t = threadIdx.x;
    if (src < 0) {
        for (int e = t; e < H_; e += 256) g_cmp[row*H_ + e] = 0.f;
    } else {
        const float* xp = g_h + (b*S_ + src)*H_;
        for (int e = t; e < H_; e += 256) g_cmp[row*H_ + e] = xp[e];
    }
}

// ---------------- classifier + softmax ---------------------------------------
__global__ __launch_bounds__(256) void clf_kernel(
    const float* __restrict__ W, const float* __restrict__ bias,
    float* __restrict__ outp)
{
    int row = blockIdx.x, t = threadIdx.x;
    __shared__ float red[256][NL_ + 1];
    float p[NL_];
    #pragma unroll
    for (int c = 0; c < NL_; c++) p[c] = 0.f;
    for (int e = t; e < H_; e += 256) {
        float x = g_cmp[row*H_ + e];
        #pragma unroll
        for (int c = 0; c < NL_; c++) p[c] = fmaf(x, W[e*NL_ + c], p[c]);
    }
    #pragma unroll
    for (int c = 0; c < NL_; c++) red[t][c] = p[c];
    __syncthreads();
    for (int st = 128; st > 0; st >>= 1) {
        if (t < st)
            #pragma unroll
            for (int c = 0; c < NL_; c++) red[t][c] += red[t+st][c];
        __syncthreads();
    }
    if (t == 0) {
        float l[NL_], mx = -1e30f, sum = 0.f;
        #pragma unroll
        for (int c = 0; c < NL_; c++) { l[c] = red[0][c] + bias[c]; mx = fmaxf(mx, l[c]); }
        #pragma unroll
        for (int c = 0; c < NL_; c++) { l[c] = expf(l[c] - mx); sum += l[c]; }
        float inv = 1.0f / sum;
        #pragma unroll
        for (int c = 0; c < NL_; c++) outp[row*NL_ + c] = l[c] * inv;
    }
}

// ---------------- launch --------------------------------------------------
extern "C" void kernel_launch(void* const* d_in, const int* in_sizes, int n_in,
                              void* d_out, int out_size)
{
    const int*   ids   = (const int*)  d_in[0];
    const int*   mask  = (const int*)  d_in[1];
    const int*   types = (const int*)  d_in[2];
    const int*   valid = (const int*)  d_in[3];
    const float* we    = (const float*)d_in[4];
    const float* pe    = (const float*)d_in[5];
    const float* te    = (const float*)d_in[6];
    const float* elg   = (const float*)d_in[7];
    const float* elb   = (const float*)d_in[8];
    const float* Wq    = (const float*)d_in[9];
    const float* bq    = (const float*)d_in[10];
    const float* Wk    = (const float*)d_in[11];
    const float* bk    = (const float*)d_in[12];
    const float* Wv    = (const float*)d_in[13];
    const float* bv    = (const float*)d_in[14];
    const float* Wo    = (const float*)d_in[15];
    const float* bo    = (const float*)d_in[16];
    const float* l1g   = (const float*)d_in[17];
    const float* l1b   = (const float*)d_in[18];
    const float* Wi    = (const float*)d_in[19];
    const float* bi    = (const float*)d_in[20];
    const float* Wo2   = (const float*)d_in[21];
    const float* bo2   = (const float*)d_in[22];
    const float* l2g   = (const float*)d_in[23];
    const float* l2b   = (const float*)d_in[24];
    const float* cW    = (const float*)d_in[25];
    const float* cb    = (const float*)d_in[26];
    float* outp = (float*)d_out;

    float *ph, *pq, *pk, *pv, *pctx, *ptmp, *pff;
    cudaGetSymbolAddress((void**)&ph,   g_h);
    cudaGetSymbolAddress((void**)&pq,   g_q);
    cudaGetSymbolAddress((void**)&pk,   g_k);
    cudaGetSymbolAddress((void**)&pv,   g_v);
    cudaGetSymbolAddress((void**)&pctx, g_ctx);
    cudaGetSymbolAddress((void**)&ptmp, g_tmp);
    cudaGetSymbolAddress((void**)&pff,  g_ff);

    embed_kernel<<<M_, 256>>>(ids, types, we, pe, te, elg, elb);
    bias_kernel<<<(M_ + 255)/256, 256>>>(mask);

    dim3 gQKV(H_ / GBN,  M_ / GBM, 3);  // (6, 32, 3)
    dim3 gH  (H_ / GBN,  M_ / GBM, 1);  // (6, 32)
    dim3 gFF (FF_ / GBN, M_ / GBM, 1);  // (24, 32)

    for (int l = 0; l < L_; l++) {
        const float* wq = Wq + (size_t)l*H_*H_;
        const float* wk = Wk + (size_t)l*H_*H_;
        const float* wv = Wv + (size_t)l*H_*H_;
        const float* wo = Wo + (size_t)l*H_*H_;
        const float* wi = Wi + (size_t)l*H_*FF_;
        const float* w2 = Wo2 + (size_t)l*FF_*H_;

        gemm_mma<<<gQKV, 256>>>(ph, wq, wk, wv,
                                bq + l*H_, bk + l*H_, bv + l*H_,
                                pq, pk, pv, nullptr, M_, H_, H_, 0);

        attn_kernel<<<dim3(S_, NH_, B_), 256>>>();

        gemm_mma<<<gH, 256>>>(pctx, wo, wo, wo,
                              bo + l*H_, bo + l*H_, bo + l*H_,
                              ptmp, ptmp, ptmp, ph, M_, H_, H_, 0);
        ln_kernel<<<M_, 256>>>(ptmp, l1g + l*H_, l1b + l*H_, ph);

        gemm_mma<<<gFF, 256>>>(ph, wi, wi, wi,
                               bi + l*FF_, bi + l*FF_, bi + l*FF_,
                               pff, pff, pff, nullptr, M_, FF_, H_, 1);
        gemm_mma<<<gH, 256>>>(pff, w2, w2, w2,
                              bo2 + l*H_, bo2 + l*H_, bo2 + l*H_,
                              ptmp, ptmp, ptmp, ph, M_, H_, FF_, 0);
        ln_kernel<<<M_, 256>>>(ptmp, l2g + l*H_, l2b + l*H_, ph);
    }

    order_kernel<<<B_, 256>>>(valid);
    compact_kernel<<<M_, 256>>>();
    clf_kernel<<<M_, 256>>>(cW, cb, outp);
}

// round 3
// speedup vs baseline: 5.3706x; 1.9717x over previous
#include <cuda_runtime.h>
#include <math.h>

#define B_  8
#define S_  256
#define H_  768
#define L_  12
#define NH_ 12
#define D_  64
#define FF_ 3072
#define NL_ 9
#define M_  (B_*S_)   // 2048 token rows

// ---------------- scratch (device globals: allowed, no allocations) ---------
__device__ float g_h  [M_*H_];
__device__ float g_q  [M_*H_];
__device__ float g_k  [M_*H_];
__device__ float g_v  [M_*H_];
__device__ float g_ctx[M_*H_];
__device__ float g_tmp[M_*H_];
__device__ float g_ff [M_*FF_];
__device__ float g_cmp[M_*H_];
__device__ float g_bias[M_];
__device__ int   g_order[M_];

// ---------------- tf32 helper ------------------------------------------------
__device__ __forceinline__ unsigned f2tf(float x) {
    unsigned r;
    asm("cvt.rna.tf32.f32 %0, %1;" : "=r"(r) : "f"(x));
    return r;
}

#define MMA_TF32(acc, a, b)                                                  \
    asm volatile(                                                            \
        "mma.sync.aligned.m16n8k8.row.col.f32.tf32.tf32.f32 "                \
        "{%0,%1,%2,%3},{%4,%5,%6,%7},{%8,%9},{%0,%1,%2,%3};\n"               \
        : "+f"(acc[0]), "+f"(acc[1]), "+f"(acc[2]), "+f"(acc[3])             \
        : "r"(a[0]), "r"(a[1]), "r"(a[2]), "r"(a[3]), "r"(b[0]), "r"(b[1]))

// ---------------- embeddings + LayerNorm ------------------------------------
__global__ __launch_bounds__(256) void embed_kernel(
    const int* __restrict__ ids, const int* __restrict__ types,
    const float* __restrict__ we, const float* __restrict__ pe,
    const float* __restrict__ te,
    const float* __restrict__ g, const float* __restrict__ bta)
{
    int row = blockIdx.x;
    int s   = row % S_;
    int t   = threadIdx.x;
    __shared__ float x[H_];
    __shared__ float red[256];

    int id = ids[row];
    int ty = types[row];
    for (int e = t; e < H_; e += 256)
        x[e] = we[id*H_ + e] + pe[s*H_ + e] + te[ty*H_ + e];
    __syncthreads();

    float lsum = 0.f;
    for (int e = t; e < H_; e += 256) lsum += x[e];
    red[t] = lsum; __syncthreads();
    for (int st = 128; st > 0; st >>= 1) { if (t < st) red[t] += red[t+st]; __syncthreads(); }
    float mean = red[0] * (1.0f / H_);
    __syncthreads();

    float lv = 0.f;
    for (int e = t; e < H_; e += 256) { float d = x[e] - mean; lv += d*d; }
    red[t] = lv; __syncthreads();
    for (int st = 128; st > 0; st >>= 1) { if (t < st) red[t] += red[t+st]; __syncthreads(); }
    float rstd = rsqrtf(red[0] * (1.0f / H_) + 1e-12f);

    for (int e = t; e < H_; e += 256)
        g_h[row*H_ + e] = (x[e] - mean) * rstd * g[e] + bta[e];
}

// ---------------- generic LayerNorm ------------------------------------------
__global__ __launch_bounds__(256) void ln_kernel(
    const float* __restrict__ in, const float* __restrict__ g,
    const float* __restrict__ bta, float* __restrict__ outp)
{
    int row = blockIdx.x;
    int t   = threadIdx.x;
    __shared__ float red[256];
    const float* xr = in + row*H_;

    float lsum = 0.f;
    for (int e = t; e < H_; e += 256) lsum += xr[e];
    red[t] = lsum; __syncthreads();
    for (int st = 128; st > 0; st >>= 1) { if (t < st) red[t] += red[t+st]; __syncthreads(); }
    float mean = red[0] * (1.0f / H_);
    __syncthreads();

    float lv = 0.f;
    for (int e = t; e < H_; e += 256) { float d = xr[e] - mean; lv += d*d; }
    red[t] = lv; __syncthreads();
    for (int st = 128; st > 0; st >>= 1) { if (t < st) red[t] += red[t+st]; __syncthreads(); }
    float rstd = rsqrtf(red[0] * (1.0f / H_) + 1e-12f);

    for (int e = t; e < H_; e += 256)
        outp[row*H_ + e] = (xr[e] - mean) * rstd * g[e] + bta[e];
}

// ---------------- attention mask bias ----------------------------------------
__global__ void bias_kernel(const int* __restrict__ mask)
{
    int i = blockIdx.x * 256 + threadIdx.x;
    if (i < M_) g_bias[i] = (1.0f - (float)mask[i]) * -1e4f;
}

// ---------------- tf32 tensor-core GEMM ---------------------------------------
#define GBM 64
#define GBN 128
#define GBK 16

__global__ __launch_bounds__(256, 2) void gemm_mma(
    const float* __restrict__ A,
    const float* __restrict__ W0, const float* __restrict__ W1, const float* __restrict__ W2,
    const float* __restrict__ bi0, const float* __restrict__ bi1, const float* __restrict__ bi2,
    float* __restrict__ C0, float* __restrict__ C1, float* __restrict__ C2,
    const float* __restrict__ res, int M, int N, int K, int act)
{
    const float* B    = (blockIdx.z == 0) ? W0 : (blockIdx.z == 1 ? W1 : W2);
    const float* bias = (blockIdx.z == 0) ? bi0 : (blockIdx.z == 1 ? bi1 : bi2);
    float*       C    = (blockIdx.z == 0) ? C0 : (blockIdx.z == 1 ? C1 : C2);

    __shared__ unsigned As[GBM][20];
    __shared__ unsigned Bs[GBK][136];

    const int tid  = threadIdx.x;
    const int row0 = blockIdx.y * GBM;
    const int col0 = blockIdx.x * GBN;

    const int ar = tid >> 2,  ac = (tid & 3) << 2;
    const int br = tid >> 5,  bc = (tid & 31) << 2;

    const int warp = tid >> 5, lane = tid & 31;
    const int wm = warp >> 2, wn = warp & 3;
    const int grp = lane >> 2, tg = lane & 3;

    float acc[2][4][4];
    #pragma unroll
    for (int i = 0; i < 2; i++)
        #pragma unroll
        for (int j = 0; j < 4; j++)
            #pragma unroll
            for (int c = 0; c < 4; c++) acc[i][j][c] = 0.f;

    const float* Abase = A + (size_t)(row0 + ar)*K + ac;
    const float* Bbase = B + (size_t)br*N + col0 + bc;

    float4 ra  = *(const float4*)(Abase);
    float4 rb0 = *(const float4*)(Bbase);
    float4 rb1 = *(const float4*)(Bbase + 8*(size_t)N);

    for (int kk = 0; kk < K; kk += GBK) {
        *(uint4*)&As[ar][ac] = make_uint4(f2tf(ra.x), f2tf(ra.y), f2tf(ra.z), f2tf(ra.w));
        *(uint4*)&Bs[br][bc] = make_uint4(f2tf(rb0.x), f2tf(rb0.y), f2tf(rb0.z), f2tf(rb0.w));
        *(uint4*)&Bs[br+8][bc] = make_uint4(f2tf(rb1.x), f2tf(rb1.y), f2tf(rb1.z), f2tf(rb1.w));
        __syncthreads();

        if (kk + GBK < K) {
            ra  = *(const float4*)(Abase + kk + GBK);
            rb0 = *(const float4*)(Bbase + (size_t)(kk + GBK)*N);
            rb1 = *(const float4*)(Bbase + (size_t)(kk + GBK + 8)*N);
        }

        #pragma unroll
        for (int k8 = 0; k8 < GBK; k8 += 8) {
            unsigned af[2][4], bf[4][2];
            #pragma unroll
            for (int mt = 0; mt < 2; mt++) {
                int r = wm*32 + mt*16 + grp;
                af[mt][0] = As[r][k8 + tg];
                af[mt][1] = As[r + 8][k8 + tg];
                af[mt][2] = As[r][k8 + tg + 4];
                af[mt][3] = As[r + 8][k8 + tg + 4];
            }
            #pragma unroll
            for (int nt = 0; nt < 4; nt++) {
                int c = wn*32 + nt*8 + grp;
                bf[nt][0] = Bs[k8 + tg][c];
                bf[nt][1] = Bs[k8 + tg + 4][c];
            }
            #pragma unroll
            for (int mt = 0; mt < 2; mt++)
                #pragma unroll
                for (int nt = 0; nt < 4; nt++)
                    MMA_TF32(acc[mt][nt], af[mt], bf[nt]);
        }
        __syncthreads();
    }

    #pragma unroll
    for (int mt = 0; mt < 2; mt++) {
        #pragma unroll
        for (int nt = 0; nt < 4; nt++) {
            int r0 = row0 + wm*32 + mt*16 + grp;
            int r1 = r0 + 8;
            int c  = col0 + wn*32 + nt*8 + 2*tg;
            float b0 = bias[c], b1 = bias[c+1];
            float v00 = acc[mt][nt][0] + b0, v01 = acc[mt][nt][1] + b1;
            float v10 = acc[mt][nt][2] + b0, v11 = acc[mt][nt][3] + b1;
            if (res) {
                v00 += res[(size_t)r0*N + c];     v01 += res[(size_t)r0*N + c + 1];
                v10 += res[(size_t)r1*N + c];     v11 += res[(size_t)r1*N + c + 1];
            }
            if (act) {
                v00 = 0.5f*v00*(1.0f + erff(v00*0.70710678118654752f));
                v01 = 0.5f*v01*(1.0f + erff(v01*0.70710678118654752f));
                v10 = 0.5f*v10*(1.0f + erff(v10*0.70710678118654752f));
                v11 = 0.5f*v11*(1.0f + erff(v11*0.70710678118654752f));
            }
            *(float2*)&C[(size_t)r0*N + c] = make_float2(v00, v01);
            *(float2*)&C[(size_t)r1*N + c] = make_float2(v10, v11);
        }
    }
}

// ---------------- fused tensor-core attention --------------------------------
// grid (S/64, NH, B), 256 threads. smem: Q(64x64) K(256x64) Vt(64x256) S(64x256)
#define QS_STRIDE 68
#define KS_STRIDE 68
#define VS_STRIDE 260
#define SS_STRIDE 260
#define ATTN_SMEM_FLOATS (64*QS_STRIDE + 256*KS_STRIDE + 64*VS_STRIDE + 64*SS_STRIDE + 256 + 64)

__global__ __launch_bounds__(256, 1) void attn_fused()
{
    const int qt = blockIdx.x, h = blockIdx.y, b = blockIdx.z;
    const int q0 = qt * 64;
    const int tid = threadIdx.x;
    const int warp = tid >> 5, lane = tid & 31;
    const int grp = lane >> 2, tg = lane & 3;
    const int wm = warp >> 2, wn = warp & 3;

    extern __shared__ float sm[];
    unsigned* Qs = (unsigned*)sm;                    // 64 x QS_STRIDE (tf32)
    unsigned* Ks = Qs + 64*QS_STRIDE;                // 256 x KS_STRIDE (tf32, [kidx][d])
    unsigned* Vt = Ks + 256*KS_STRIDE;               // 64 x VS_STRIDE (tf32, [d][kidx])
    float*    Ss = (float*)(Vt + 64*VS_STRIDE);      // 64 x SS_STRIDE
    unsigned* Su = (unsigned*)Ss;
    float*    bias_s = Ss + 64*SS_STRIDE;            // 256
    float*    inv_s  = bias_s + 256;                 // 64

    // ---- stage Q tile (64x64), K (256x64), V^T (64x256) as tf32 ----
    const float* Qg = g_q + ((size_t)(b*S_ + q0))*H_ + h*D_;
    #pragma unroll
    for (int i = 0; i < 4; i++) {
        int fi = i*256 + tid;
        int r = fi >> 4, c4 = (fi & 15) << 2;
        float4 v = *(const float4*)(Qg + (size_t)r*H_ + c4);
        *(uint4*)&Qs[r*QS_STRIDE + c4] =
            make_uint4(f2tf(v.x), f2tf(v.y), f2tf(v.z), f2tf(v.w));
    }
    const float* Kg = g_k + ((size_t)(b*S_))*H_ + h*D_;
    #pragma unroll
    for (int i = 0; i < 16; i++) {
        int fi = i*256 + tid;
        int r = fi >> 4, c4 = (fi & 15) << 2;
        float4 v = *(const float4*)(Kg + (size_t)r*H_ + c4);
        *(uint4*)&Ks[r*KS_STRIDE + c4] =
            make_uint4(f2tf(v.x), f2tf(v.y), f2tf(v.z), f2tf(v.w));
    }
    const float* Vg = g_v + ((size_t)(b*S_))*H_ + h*D_;
    #pragma unroll
    for (int i = 0; i < 16; i++) {
        int fi = i*256 + tid;
        int k = fi >> 4, d4 = (fi & 15) << 2;
        float4 v = *(const float4*)(Vg + (size_t)k*H_ + d4);
        Vt[(d4+0)*VS_STRIDE + k] = f2tf(v.x);
        Vt[(d4+1)*VS_STRIDE + k] = f2tf(v.y);
        Vt[(d4+2)*VS_STRIDE + k] = f2tf(v.z);
        Vt[(d4+3)*VS_STRIDE + k] = f2tf(v.w);
    }
    bias_s[tid] = g_bias[b*S_ + tid];
    __syncthreads();

    // ---- phase 1: scores = Q @ K^T  (M=64, N=256, K=64) ----
    float acc1[2][8][4];
    #pragma unroll
    for (int mt = 0; mt < 2; mt++)
        #pragma unroll
        for (int nt = 0; nt < 8; nt++)
            #pragma unroll
            for (int c = 0; c < 4; c++) acc1[mt][nt][c] = 0.f;

    #pragma unroll
    for (int k8 = 0; k8 < 64; k8 += 8) {
        unsigned af[2][4], bf[8][2];
        #pragma unroll
        for (int mt = 0; mt < 2; mt++) {
            int r = wm*32 + mt*16 + grp;
            af[mt][0] = Qs[r*QS_STRIDE + k8 + tg];
            af[mt][1] = Qs[(r+8)*QS_STRIDE + k8 + tg];
            af[mt][2] = Qs[r*QS_STRIDE + k8 + tg + 4];
            af[mt][3] = Qs[(r+8)*QS_STRIDE + k8 + tg + 4];
        }
        #pragma unroll
        for (int nt = 0; nt < 8; nt++) {
            int c = wn*64 + nt*8 + grp;
            bf[nt][0] = Ks[c*KS_STRIDE + k8 + tg];
            bf[nt][1] = Ks[c*KS_STRIDE + k8 + tg + 4];
        }
        #pragma unroll
        for (int mt = 0; mt < 2; mt++)
            #pragma unroll
            for (int nt = 0; nt < 8; nt++)
                MMA_TF32(acc1[mt][nt], af[mt], bf[nt]);
    }

    // scores -> smem with scale + mask bias
    #pragma unroll
    for (int mt = 0; mt < 2; mt++) {
        int lr0 = wm*32 + mt*16 + grp, lr1 = lr0 + 8;
        #pragma unroll
        for (int nt = 0; nt < 8; nt++) {
            int c = wn*64 + nt*8 + 2*tg;
            float b0 = bias_s[c], b1 = bias_s[c+1];
            Ss[lr0*SS_STRIDE + c]     = acc1[mt][nt][0]*0.125f + b0;
            Ss[lr0*SS_STRIDE + c + 1] = acc1[mt][nt][1]*0.125f + b1;
            Ss[lr1*SS_STRIDE + c]     = acc1[mt][nt][2]*0.125f + b0;
            Ss[lr1*SS_STRIDE + c + 1] = acc1[mt][nt][3]*0.125f + b1;
        }
    }
    __syncthreads();

    // ---- softmax: warp w handles rows 8w..8w+7 ----
    #pragma unroll
    for (int rr = 0; rr < 8; rr++) {
        int r = warp*8 + rr;
        float v[8], mx = -1e30f;
        #pragma unroll
        for (int i = 0; i < 8; i++) { v[i] = Ss[r*SS_STRIDE + lane + 32*i]; mx = fmaxf(mx, v[i]); }
        #pragma unroll
        for (int o = 16; o > 0; o >>= 1) mx = fmaxf(mx, __shfl_xor_sync(0xffffffffu, mx, o));
        float sum = 0.f;
        #pragma unroll
        for (int i = 0; i < 8; i++) { v[i] = __expf(v[i] - mx); sum += v[i]; }
        #pragma unroll
        for (int o = 16; o > 0; o >>= 1) sum += __shfl_xor_sync(0xffffffffu, sum, o);
        #pragma unroll
        for (int i = 0; i < 8; i++) Su[r*SS_STRIDE + lane + 32*i] = f2tf(v[i]);
        if (lane == 0) inv_s[r] = 1.0f / sum;
    }
    __syncthreads();

    // ---- phase 2: ctx = P @ V  (M=64, N=64, K=256) ----
    float acc2[2][2][4];
    #pragma unroll
    for (int mt = 0; mt < 2; mt++)
        #pragma unroll
        for (int nt = 0; nt < 2; nt++)
            #pragma unroll
            for (int c = 0; c < 4; c++) acc2[mt][nt][c] = 0.f;

    #pragma unroll 4
    for (int k8 = 0; k8 < 256; k8 += 8) {
        unsigned af[2][4], bf[2][2];
        #pragma unroll
        for (int mt = 0; mt < 2; mt++) {
            int r = wm*32 + mt*16 + grp;
            af[mt][0] = Su[r*SS_STRIDE + k8 + tg];
            af[mt][1] = Su[(r+8)*SS_STRIDE + k8 + tg];
            af[mt][2] = Su[r*SS_STRIDE + k8 + tg + 4];
            af[mt][3] = Su[(r+8)*SS_STRIDE + k8 + tg + 4];
        }
        #pragma unroll
        for (int nt = 0; nt < 2; nt++) {
            int c = wn*16 + nt*8 + grp;
            bf[nt][0] = Vt[c*VS_STRIDE + k8 + tg];
            bf[nt][1] = Vt[c*VS_STRIDE + k8 + tg + 4];
        }
        #pragma unroll
        for (int mt = 0; mt < 2; mt++)
            #pragma unroll
            for (int nt = 0; nt < 2; nt++)
                MMA_TF32(acc2[mt][nt], af[mt], bf[nt]);
    }

    #pragma unroll
    for (int mt = 0; mt < 2; mt++) {
        int lr0 = wm*32 + mt*16 + grp, lr1 = lr0 + 8;
        float i0 = inv_s[lr0], i1 = inv_s[lr1];
        #pragma unroll
        for (int nt = 0; nt < 2; nt++) {
            int c = wn*16 + nt*8 + 2*tg;
            float* o0 = g_ctx + ((size_t)(b*S_ + q0 + lr0))*H_ + h*D_ + c;
            float* o1 = g_ctx + ((size_t)(b*S_ + q0 + lr1))*H_ + h*D_ + c;
            *(float2*)o0 = make_float2(acc2[mt][nt][0]*i0, acc2[mt][nt][1]*i0);
            *(float2*)o1 = make_float2(acc2[mt][nt][2]*i1, acc2[mt][nt][3]*i1);
        }
    }
}

// ---------------- stable compaction order per batch --------------------------
__global__ __launch_bounds__(256) void order_kernel(const int* __restrict__ valid)
{
    int b = blockIdx.x, t = threadIdx.x;
    __shared__ int sc[256];
    __shared__ int ord[256];
    int v = valid[b*S_ + t];
    sc[t] = v; __syncthreads();
    for (int off = 1; off < 256; off <<= 1) {
        int x = (t >= off) ? sc[t - off] : 0;
        __syncthreads();
        sc[t] += x;
        __syncthreads();
    }
    ord[t] = -1; __syncthreads();
    if (v) ord[sc[t] - v] = t;
    __syncthreads();
    g_order[b*S_ + t] = ord[t];
}

__global__ __launch_bounds__(256) void compact_kernel()
{
    int row = blockIdx.x;
    int b = row / S_;
    int src = g_order[row];
    int t = threadIdx.x;
    if (src < 0) {
        for (int e = t; e < H_; e += 256) g_cmp[row*H_ + e] = 0.f;
    } else {
        const float* xp = g_h + (b*S_ + src)*H_;
        for (int e = t; e < H_; e += 256) g_cmp[row*H_ + e] = xp[e];
    }
}

// ---------------- classifier + softmax ---------------------------------------
__global__ __launch_bounds__(256) void clf_kernel(
    const float* __restrict__ W, const float* __restrict__ bias,
    float* __restrict__ outp)
{
    int row = blockIdx.x, t = threadIdx.x;
    __shared__ float red[256][NL_ + 1];
    float p[NL_];
    #pragma unroll
    for (int c = 0; c < NL_; c++) p[c] = 0.f;
    for (int e = t; e < H_; e += 256) {
        float x = g_cmp[row*H_ + e];
        #pragma unroll
        for (int c = 0; c < NL_; c++) p[c] = fmaf(x, W[e*NL_ + c], p[c]);
    }
    #pragma unroll
    for (int c = 0; c < NL_; c++) red[t][c] = p[c];
    __syncthreads();
    for (int st = 128; st > 0; st >>= 1) {
        if (t < st)
            #pragma unroll
            for (int c = 0; c < NL_; c++) red[t][c] += red[t+st][c];
        __syncthreads();
    }
    if (t == 0) {
        float l[NL_], mx = -1e30f, sum = 0.f;
        #pragma unroll
        for (int c = 0; c < NL_; c++) { l[c] = red[0][c] + bias[c]; mx = fmaxf(mx, l[c]); }
        #pragma unroll
        for (int c = 0; c < NL_; c++) { l[c] = expf(l[c] - mx); sum += l[c]; }
        float inv = 1.0f / sum;
        #pragma unroll
        for (int c = 0; c < NL_; c++) outp[row*NL_ + c] = l[c] * inv;
    }
}

// ---------------- launch --------------------------------------------------
extern "C" void kernel_launch(void* const* d_in, const int* in_sizes, int n_in,
                              void* d_out, int out_size)
{
    const int*   ids   = (const int*)  d_in[0];
    const int*   mask  = (const int*)  d_in[1];
    const int*   types = (const int*)  d_in[2];
    const int*   valid = (const int*)  d_in[3];
    const float* we    = (const float*)d_in[4];
    const float* pe    = (const float*)d_in[5];
    const float* te    = (const float*)d_in[6];
    const float* elg   = (const float*)d_in[7];
    const float* elb   = (const float*)d_in[8];
    const float* Wq    = (const float*)d_in[9];
    const float* bq    = (const float*)d_in[10];
    const float* Wk    = (const float*)d_in[11];
    const float* bk    = (const float*)d_in[12];
    const float* Wv    = (const float*)d_in[13];
    const float* bv    = (const float*)d_in[14];
    const float* Wo    = (const float*)d_in[15];
    const float* bo    = (const float*)d_in[16];
    const float* l1g   = (const float*)d_in[17];
    const float* l1b   = (const float*)d_in[18];
    const float* Wi    = (const float*)d_in[19];
    const float* bi    = (const float*)d_in[20];
    const float* Wo2   = (const float*)d_in[21];
    const float* bo2   = (const float*)d_in[22];
    const float* l2g   = (const float*)d_in[23];
    const float* l2b   = (const float*)d_in[24];
    const float* cW    = (const float*)d_in[25];
    const float* cb    = (const float*)d_in[26];
    float* outp = (float*)d_out;

    float *ph, *pq, *pk, *pv, *pctx, *ptmp, *pff;
    cudaGetSymbolAddress((void**)&ph,   g_h);
    cudaGetSymbolAddress((void**)&pq,   g_q);
    cudaGetSymbolAddress((void**)&pk,   g_k);
    cudaGetSymbolAddress((void**)&pv,   g_v);
    cudaGetSymbolAddress((void**)&pctx, g_ctx);
    cudaGetSymbolAddress((void**)&ptmp, g_tmp);
    cudaGetSymbolAddress((void**)&pff,  g_ff);

    const int attn_smem = ATTN_SMEM_FLOATS * 4;   // 221,440 bytes
    cudaFuncSetAttribute(attn_fused,
                         cudaFuncAttributeMaxDynamicSharedMemorySize, attn_smem);

    embed_kernel<<<M_, 256>>>(ids, types, we, pe, te, elg, elb);
    bias_kernel<<<(M_ + 255)/256, 256>>>(mask);

    dim3 gQKV(H_ / GBN,  M_ / GBM, 3);
    dim3 gH  (H_ / GBN,  M_ / GBM, 1);
    dim3 gFF (FF_ / GBN, M_ / GBM, 1);

    for (int l = 0; l < L_; l++) {
        const float* wq = Wq + (size_t)l*H_*H_;
        const float* wk = Wk + (size_t)l*H_*H_;
        const float* wv = Wv + (size_t)l*H_*H_;
        const float* wo = Wo + (size_t)l*H_*H_;
        const float* wi = Wi + (size_t)l*H_*FF_;
        const float* w2 = Wo2 + (size_t)l*FF_*H_;

        gemm_mma<<<gQKV, 256>>>(ph, wq, wk, wv,
                                bq + l*H_, bk + l*H_, bv + l*H_,
                                pq, pk, pv, nullptr, M_, H_, H_, 0);

        attn_fused<<<dim3(S_/64, NH_, B_), 256, attn_smem>>>();

        gemm_mma<<<gH, 256>>>(pctx, wo, wo, wo,
                              bo + l*H_, bo + l*H_, bo + l*H_,
                              ptmp, ptmp, ptmp, ph, M_, H_, H_, 0);
        ln_kernel<<<M_, 256>>>(ptmp, l1g + l*H_, l1b + l*H_, ph);

        gemm_mma<<<gFF, 256>>>(ph, wi, wi, wi,
                               bi + l*FF_, bi + l*FF_, bi + l*FF_,
                               pff, pff, pff, nullptr, M_, FF_, H_, 1);
        gemm_mma<<<gH, 256>>>(pff, w2, w2, w2,
                              bo2 + l*H_, bo2 + l*H_, bo2 + l*H_,
                              ptmp, ptmp, ptmp, ph, M_, H_, FF_, 0);
        ln_kernel<<<M_, 256>>>(ptmp, l2g + l*H_, l2b + l*H_, ph);
    }

    order_kernel<<<B_, 256>>>(valid);
    compact_kernel<<<M_, 256>>>();
    clf_kernel<<<M_, 256>>>(cW, cb, outp);
}

// round 4
// speedup vs baseline: 7.5180x; 1.3999x over previous
#include <cuda_runtime.h>
#include <math.h>

#define B_  8
#define S_  256
#define H_  768
#define L_  12
#define NH_ 12
#define D_  64
#define FF_ 3072
#define NL_ 9
#define M_  (B_*S_)   // 2048 token rows

// ---------------- scratch (device globals: allowed, no allocations) ---------
__device__ float g_h  [M_*H_];
__device__ float g_q  [M_*H_];
__device__ float g_k  [M_*H_];
__device__ float g_v  [M_*H_];
__device__ float g_ctx[M_*H_];
__device__ float g_tmp[M_*H_];
__device__ float g_ff [M_*FF_];
__device__ float g_cmp[M_*H_];
__device__ float g_bias[M_];
__device__ int   g_order[M_];

// ---------------- helpers ------------------------------------------------
__device__ __forceinline__ unsigned f2tf(float x) {
    unsigned r;
    asm("cvt.rna.tf32.f32 %0, %1;" : "=r"(r) : "f"(x));
    return r;
}

#define MMA_TF32(acc, a, b)                                                  \
    asm volatile(                                                            \
        "mma.sync.aligned.m16n8k8.row.col.f32.tf32.tf32.f32 "                \
        "{%0,%1,%2,%3},{%4,%5,%6,%7},{%8,%9},{%0,%1,%2,%3};\n"               \
        : "+f"(acc[0]), "+f"(acc[1]), "+f"(acc[2]), "+f"(acc[3])             \
        : "r"(a[0]), "r"(a[1]), "r"(a[2]), "r"(a[3]), "r"(b[0]), "r"(b[1]))

__device__ __forceinline__ void cp16(void* smem, const void* g) {
    unsigned s = (unsigned)__cvta_generic_to_shared(smem);
    asm volatile("cp.async.cg.shared.global [%0], [%1], 16;\n" :: "r"(s), "l"(g));
}
__device__ __forceinline__ void cp_commit() {
    asm volatile("cp.async.commit_group;\n");
}
template<int N> __device__ __forceinline__ void cp_wait() {
    asm volatile("cp.async.wait_group %0;\n" :: "n"(N));
}

// ---------------- embeddings + LayerNorm ------------------------------------
__global__ __launch_bounds__(256) void embed_kernel(
    const int* __restrict__ ids, const int* __restrict__ types,
    const float* __restrict__ we, const float* __restrict__ pe,
    const float* __restrict__ te,
    const float* __restrict__ g, const float* __restrict__ bta)
{
    int row = blockIdx.x;
    int s   = row % S_;
    int t   = threadIdx.x;
    __shared__ float x[H_];
    __shared__ float red[256];

    int id = ids[row];
    int ty = types[row];
    for (int e = t; e < H_; e += 256)
        x[e] = we[id*H_ + e] + pe[s*H_ + e] + te[ty*H_ + e];
    __syncthreads();

    float lsum = 0.f;
    for (int e = t; e < H_; e += 256) lsum += x[e];
    red[t] = lsum; __syncthreads();
    for (int st = 128; st > 0; st >>= 1) { if (t < st) red[t] += red[t+st]; __syncthreads(); }
    float mean = red[0] * (1.0f / H_);
    __syncthreads();

    float lv = 0.f;
    for (int e = t; e < H_; e += 256) { float d = x[e] - mean; lv += d*d; }
    red[t] = lv; __syncthreads();
    for (int st = 128; st > 0; st >>= 1) { if (t < st) red[t] += red[t+st]; __syncthreads(); }
    float rstd = rsqrtf(red[0] * (1.0f / H_) + 1e-12f);

    for (int e = t; e < H_; e += 256)
        g_h[row*H_ + e] = (x[e] - mean) * rstd * g[e] + bta[e];
}

// ---------------- generic LayerNorm ------------------------------------------
__global__ __launch_bounds__(256) void ln_kernel(
    const float* __restrict__ in, const float* __restrict__ g,
    const float* __restrict__ bta, float* __restrict__ outp)
{
    int row = blockIdx.x;
    int t   = threadIdx.x;
    __shared__ float red[256];
    const float* xr = in + row*H_;

    float lsum = 0.f;
    for (int e = t; e < H_; e += 256) lsum += xr[e];
    red[t] = lsum; __syncthreads();
    for (int st = 128; st > 0; st >>= 1) { if (t < st) red[t] += red[t+st]; __syncthreads(); }
    float mean = red[0] * (1.0f / H_);
    __syncthreads();

    float lv = 0.f;
    for (int e = t; e < H_; e += 256) { float d = xr[e] - mean; lv += d*d; }
    red[t] = lv; __syncthreads();
    for (int st = 128; st > 0; st >>= 1) { if (t < st) red[t] += red[t+st]; __syncthreads(); }
    float rstd = rsqrtf(red[0] * (1.0f / H_) + 1e-12f);

    for (int e = t; e < H_; e += 256)
        outp[row*H_ + e] = (xr[e] - mean) * rstd * g[e] + bta[e];
}

// ---------------- attention mask bias ----------------------------------------
__global__ void bias_kernel(const int* __restrict__ mask)
{
    int i = blockIdx.x * 256 + threadIdx.x;
    if (i < M_) g_bias[i] = (1.0f - (float)mask[i]) * -1e4f;
}

// ---------------- cp.async double-buffered tf32 GEMM -------------------------
// C = A(MxK) @ B(KxN) + bias (+res) (+gelu). BN=128, BK=32, 256 threads.
// BM is 64 (MT=2) or 128 (MT=4). grid.z selects among 3 (W,bias,C) triples.
// Raw fp32 bits are fed to tf32 MMA (HW truncation) -> no conversion pass.
#define AST 36    // A smem row stride (floats): bank = 4*grp+tg, conflict-free
#define BST 136   // B smem row stride (floats): bank = 8*tg+grp, conflict-free

template<int BM, int MT>
__global__ __launch_bounds__(256) void gemm_cp(
    const float* __restrict__ A,
    const float* __restrict__ W0, const float* __restrict__ W1, const float* __restrict__ W2,
    const float* __restrict__ bi0, const float* __restrict__ bi1, const float* __restrict__ bi2,
    float* __restrict__ C0, float* __restrict__ C1, float* __restrict__ C2,
    const float* __restrict__ res, int M, int N, int K, int act)
{
    const float* Bw   = (blockIdx.z == 0) ? W0 : (blockIdx.z == 1 ? W1 : W2);
    const float* bias = (blockIdx.z == 0) ? bi0 : (blockIdx.z == 1 ? bi1 : bi2);
    float*       C    = (blockIdx.z == 0) ? C0 : (blockIdx.z == 1 ? C1 : C2);

    constexpr int ASZ = BM * AST;     // floats per A buffer
    constexpr int BSZ = 32 * BST;     // floats per B buffer
    extern __shared__ float sm[];

    const int tid  = threadIdx.x;
    const int row0 = blockIdx.y * BM;
    const int col0 = blockIdx.x * 128;

    const int warp = tid >> 5, lane = tid & 31;
    const int wm = warp >> 2, wn = warp & 3;
    const int grp = lane >> 2, tg = lane & 3;

    float acc[MT][4][4];
    #pragma unroll
    for (int mt = 0; mt < MT; mt++)
        #pragma unroll
        for (int nt = 0; nt < 4; nt++)
            #pragma unroll
            for (int c = 0; c < 4; c++) acc[mt][nt][c] = 0.f;

    const float* Ag = A  + (size_t)row0 * K;
    const float* Bg = Bw + col0;

    auto issue = [&](int it, int buf) {
        float* As = sm + buf * (ASZ + BSZ);
        float* Bs = As + ASZ;
        const int kk = it * 32;
        #pragma unroll
        for (int p = 0; p < BM*8/256; p++) {            // A: BM rows x 32 cols
            int idx = tid + p*256;
            int m = idx >> 3, k4 = (idx & 7) << 2;
            cp16(&As[m*AST + k4], Ag + (size_t)m*K + kk + k4);
        }
        #pragma unroll
        for (int p = 0; p < 4; p++) {                   // B: 32 rows x 128 cols
            int idx = tid + p*256;
            int k = idx >> 5, n4 = (idx & 31) << 2;
            cp16(&Bs[k*BST + n4], Bg + (size_t)(kk + k)*N + n4);
        }
        cp_commit();
    };

    const int nIter = K >> 5;
    issue(0, 0);

    for (int it = 0; it < nIter; it++) {
        const int buf = it & 1;
        if (it + 1 < nIter) { issue(it + 1, buf ^ 1); cp_wait<1>(); }
        else                { cp_wait<0>(); }
        __syncthreads();

        const unsigned* Au = (const unsigned*)(sm + buf * (ASZ + BSZ));
        const unsigned* Bu = Au + ASZ;

        #pragma unroll
        for (int k8 = 0; k8 < 32; k8 += 8) {
            unsigned af[MT][4], bf[4][2];
            #pragma unroll
            for (int mt = 0; mt < MT; mt++) {
                const unsigned* Ar = Au + (wm*(BM/2) + mt*16 + grp)*AST;
                af[mt][0] = Ar[k8 + tg];
                af[mt][1] = Ar[8*AST + k8 + tg];
                af[mt][2] = Ar[k8 + tg + 4];
                af[mt][3] = Ar[8*AST + k8 + tg + 4];
            }
            #pragma unroll
            for (int nt = 0; nt < 4; nt++) {
                int c = wn*32 + nt*8 + grp;
                bf[nt][0] = Bu[(k8 + tg)*BST + c];
                bf[nt][1] = Bu[(k8 + tg + 4)*BST + c];
            }
            #pragma unroll
            for (int mt = 0; mt < MT; mt++)
                #pragma unroll
                for (int nt = 0; nt < 4; nt++)
                    MMA_TF32(acc[mt][nt], af[mt], bf[nt]);
        }
        __syncthreads();
    }

    #pragma unroll
    for (int mt = 0; mt < MT; mt++) {
        #pragma unroll
        for (int nt = 0; nt < 4; nt++) {
            int r0 = row0 + wm*(BM/2) + mt*16 + grp;
            int r1 = r0 + 8;
            int c  = col0 + wn*32 + nt*8 + 2*tg;
            float b0 = bias[c], b1 = bias[c+1];
            float v00 = acc[mt][nt][0] + b0, v01 = acc[mt][nt][1] + b1;
            float v10 = acc[mt][nt][2] + b0, v11 = acc[mt][nt][3] + b1;
            if (res) {
                v00 += res[(size_t)r0*N + c];     v01 += res[(size_t)r0*N + c + 1];
                v10 += res[(size_t)r1*N + c];     v11 += res[(size_t)r1*N + c + 1];
            }
            if (act) {
                v00 = 0.5f*v00*(1.0f + erff(v00*0.70710678118654752f));
                v01 = 0.5f*v01*(1.0f + erff(v01*0.70710678118654752f));
                v10 = 0.5f*v10*(1.0f + erff(v10*0.70710678118654752f));
                v11 = 0.5f*v11*(1.0f + erff(v11*0.70710678118654752f));
            }
            *(float2*)&C[(size_t)r0*N + c] = make_float2(v00, v01);
            *(float2*)&C[(size_t)r1*N + c] = make_float2(v10, v11);
        }
    }
}

// ---------------- fused tensor-core attention --------------------------------
#define QS_STRIDE 68
#define KS_STRIDE 68
#define VS_STRIDE 260
#define SS_STRIDE 260
#define ATTN_SMEM_FLOATS (64*QS_STRIDE + 256*KS_STRIDE + 64*VS_STRIDE + 64*SS_STRIDE + 256 + 64)

__global__ __launch_bounds__(256, 1) void attn_fused()
{
    const int qt = blockIdx.x, h = blockIdx.y, b = blockIdx.z;
    const int q0 = qt * 64;
    const int tid = threadIdx.x;
    const int warp = tid >> 5, lane = tid & 31;
    const int grp = lane >> 2, tg = lane & 3;
    const int wm = warp >> 2, wn = warp & 3;

    extern __shared__ float sm[];
    unsigned* Qs = (unsigned*)sm;
    unsigned* Ks = Qs + 64*QS_STRIDE;
    unsigned* Vt = Ks + 256*KS_STRIDE;
    float*    Ss = (float*)(Vt + 64*VS_STRIDE);
    unsigned* Su = (unsigned*)Ss;
    float*    bias_s = Ss + 64*SS_STRIDE;
    float*    inv_s  = bias_s + 256;

    const float* Qg = g_q + ((size_t)(b*S_ + q0))*H_ + h*D_;
    #pragma unroll
    for (int i = 0; i < 4; i++) {
        int fi = i*256 + tid;
        int r = fi >> 4, c4 = (fi & 15) << 2;
        float4 v = *(const float4*)(Qg + (size_t)r*H_ + c4);
        *(uint4*)&Qs[r*QS_STRIDE + c4] =
            make_uint4(f2tf(v.x), f2tf(v.y), f2tf(v.z), f2tf(v.w));
    }
    const float* Kg = g_k + ((size_t)(b*S_))*H_ + h*D_;
    #pragma unroll
    for (int i = 0; i < 16; i++) {
        int fi = i*256 + tid;
        int r = fi >> 4, c4 = (fi & 15) << 2;
        float4 v = *(const float4*)(Kg + (size_t)r*H_ + c4);
        *(uint4*)&Ks[r*KS_STRIDE + c4] =
            make_uint4(f2tf(v.x), f2tf(v.y), f2tf(v.z), f2tf(v.w));
    }
    const float* Vg = g_v + ((size_t)(b*S_))*H_ + h*D_;
    #pragma unroll
    for (int i = 0; i < 16; i++) {
        int fi = i*256 + tid;
        int k = fi >> 4, d4 = (fi & 15) << 2;
        float4 v = *(const float4*)(Vg + (size_t)k*H_ + d4);
        Vt[(d4+0)*VS_STRIDE + k] = f2tf(v.x);
        Vt[(d4+1)*VS_STRIDE + k] = f2tf(v.y);
        Vt[(d4+2)*VS_STRIDE + k] = f2tf(v.z);
        Vt[(d4+3)*VS_STRIDE + k] = f2tf(v.w);
    }
    bias_s[tid] = g_bias[b*S_ + tid];
    __syncthreads();

    // phase 1: scores = Q @ K^T
    float acc1[2][8][4];
    #pragma unroll
    for (int mt = 0; mt < 2; mt++)
        #pragma unroll
        for (int nt = 0; nt < 8; nt++)
            #pragma unroll
            for (int c = 0; c < 4; c++) acc1[mt][nt][c] = 0.f;

    #pragma unroll
    for (int k8 = 0; k8 < 64; k8 += 8) {
        unsigned af[2][4], bf[8][2];
        #pragma unroll
        for (int mt = 0; mt < 2; mt++) {
            int r = wm*32 + mt*16 + grp;
            af[mt][0] = Qs[r*QS_STRIDE + k8 + tg];
            af[mt][1] = Qs[(r+8)*QS_STRIDE + k8 + tg];
            af[mt][2] = Qs[r*QS_STRIDE + k8 + tg + 4];
            af[mt][3] = Qs[(r+8)*QS_STRIDE + k8 + tg + 4];
        }
        #pragma unroll
        for (int nt = 0; nt < 8; nt++) {
            int c = wn*64 + nt*8 + grp;
            bf[nt][0] = Ks[c*KS_STRIDE + k8 + tg];
            bf[nt][1] = Ks[c*KS_STRIDE + k8 + tg + 4];
        }
        #pragma unroll
        for (int mt = 0; mt < 2; mt++)
            #pragma unroll
            for (int nt = 0; nt < 8; nt++)
                MMA_TF32(acc1[mt][nt], af[mt], bf[nt]);
    }

    #pragma unroll
    for (int mt = 0; mt < 2; mt++) {
        int lr0 = wm*32 + mt*16 + grp, lr1 = lr0 + 8;
        #pragma unroll
        for (int nt = 0; nt < 8; nt++) {
            int c = wn*64 + nt*8 + 2*tg;
            float b0 = bias_s[c], b1 = bias_s[c+1];
            Ss[lr0*SS_STRIDE + c]     = acc1[mt][nt][0]*0.125f + b0;
            Ss[lr0*SS_STRIDE + c + 1] = acc1[mt][nt][1]*0.125f + b1;
            Ss[lr1*SS_STRIDE + c]     = acc1[mt][nt][2]*0.125f + b0;
            Ss[lr1*SS_STRIDE + c + 1] = acc1[mt][nt][3]*0.125f + b1;
        }
    }
    __syncthreads();

    // softmax
    #pragma unroll
    for (int rr = 0; rr < 8; rr++) {
        int r = warp*8 + rr;
        float v[8], mx = -1e30f;
        #pragma unroll
        for (int i = 0; i < 8; i++) { v[i] = Ss[r*SS_STRIDE + lane + 32*i]; mx = fmaxf(mx, v[i]); }
        #pragma unroll
        for (int o = 16; o > 0; o >>= 1) mx = fmaxf(mx, __shfl_xor_sync(0xffffffffu, mx, o));
        float sum = 0.f;
        #pragma unroll
        for (int i = 0; i < 8; i++) { v[i] = __expf(v[i] - mx); sum += v[i]; }
        #pragma unroll
        for (int o = 16; o > 0; o >>= 1) sum += __shfl_xor_sync(0xffffffffu, sum, o);
        #pragma unroll
        for (int i = 0; i < 8; i++) Su[r*SS_STRIDE + lane + 32*i] = f2tf(v[i]);
        if (lane == 0) inv_s[r] = 1.0f / sum;
    }
    __syncthreads();

    // phase 2: ctx = P @ V
    float acc2[2][2][4];
    #pragma unroll
    for (int mt = 0; mt < 2; mt++)
        #pragma unroll
        for (int nt = 0; nt < 2; nt++)
            #pragma unroll
            for (int c = 0; c < 4; c++) acc2[mt][nt][c] = 0.f;

    #pragma unroll 4
    for (int k8 = 0; k8 < 256; k8 += 8) {
        unsigned af[2][4], bf[2][2];
        #pragma unroll
        for (int mt = 0; mt < 2; mt++) {
            int r = wm*32 + mt*16 + grp;
            af[mt][0] = Su[r*SS_STRIDE + k8 + tg];
            af[mt][1] = Su[(r+8)*SS_STRIDE + k8 + tg];
            af[mt][2] = Su[r*SS_STRIDE + k8 + tg + 4];
            af[mt][3] = Su[(r+8)*SS_STRIDE + k8 + tg + 4];
        }
        #pragma unroll
        for (int nt = 0; nt < 2; nt++) {
            int c = wn*16 + nt*8 + grp;
            bf[nt][0] = Vt[c*VS_STRIDE + k8 + tg];
            bf[nt][1] = Vt[c*VS_STRIDE + k8 + tg + 4];
        }
        #pragma unroll
        for (int mt = 0; mt < 2; mt++)
            #pragma unroll
            for (int nt = 0; nt < 2; nt++)
                MMA_TF32(acc2[mt][nt], af[mt], bf[nt]);
    }

    #pragma unroll
    for (int mt = 0; mt < 2; mt++) {
        int lr0 = wm*32 + mt*16 + grp, lr1 = lr0 + 8;
        float i0 = inv_s[lr0], i1 = inv_s[lr1];
        #pragma unroll
        for (int nt = 0; nt < 2; nt++) {
            int c = wn*16 + nt*8 + 2*tg;
            float* o0 = g_ctx + ((size_t)(b*S_ + q0 + lr0))*H_ + h*D_ + c;
            float* o1 = g_ctx + ((size_t)(b*S_ + q0 + lr1))*H_ + h*D_ + c;
            *(float2*)o0 = make_float2(acc2[mt][nt][0]*i0, acc2[mt][nt][1]*i0);
            *(float2*)o1 = make_float2(acc2[mt][nt][2]*i1, acc2[mt][nt][3]*i1);
        }
    }
}

// ---------------- stable compaction order per batch --------------------------
__global__ __launch_bounds__(256) void order_kernel(const int* __restrict__ valid)
{
    int b = blockIdx.x, t = threadIdx.x;
    __shared__ int sc[256];
    __shared__ int ord[256];
    int v = valid[b*S_ + t];
    sc[t] = v; __syncthreads();
    for (int off = 1; off < 256; off <<= 1) {
        int x = (t >= off) ? sc[t - off] : 0;
        __syncthreads();
        sc[t] += x;
        __syncthreads();
    }
    ord[t] = -1; __syncthreads();
    if (v) ord[sc[t] - v] = t;
    __syncthreads();
    g_order[b*S_ + t] = ord[t];
}

__global__ __launch_bounds__(256) void compact_kernel()
{
    int row = blockIdx.x;
    int b = row / S_;
    int src = g_order[row];
    int t = threadIdx.x;
    if (src < 0) {
        for (int e = t; e < H_; e += 256) g_cmp[row*H_ + e] = 0.f;
    } else {
        const float* xp = g_h + (b*S_ + src)*H_;
        for (int e = t; e < H_; e += 256) g_cmp[row*H_ + e] = xp[e];
    }
}

// ---------------- classifier + softmax ---------------------------------------
__global__ __launch_bounds__(256) void clf_kernel(
    const float* __restrict__ W, const float* __restrict__ bias,
    float* __restrict__ outp)
{
    int row = blockIdx.x, t = threadIdx.x;
    __shared__ float red[256][NL_ + 1];
    float p[NL_];
    #pragma unroll
    for (int c = 0; c < NL_; c++) p[c] = 0.f;
    for (int e = t; e < H_; e += 256) {
        float x = g_cmp[row*H_ + e];
        #pragma unroll
        for (int c = 0; c < NL_; c++) p[c] = fmaf(x, W[e*NL_ + c], p[c]);
    }
    #pragma unroll
    for (int c = 0; c < NL_; c++) red[t][c] = p[c];
    __syncthreads();
    for (int st = 128; st > 0; st >>= 1) {
        if (t < st)
            #pragma unroll
            for (int c = 0; c < NL_; c++) red[t][c] += red[t+st][c];
        __syncthreads();
    }
    if (t == 0) {
        float l[NL_], mx = -1e30f, sum = 0.f;
        #pragma unroll
        for (int c = 0; c < NL_; c++) { l[c] = red[0][c] + bias[c]; mx = fmaxf(mx, l[c]); }
        #pragma unroll
        for (int c = 0; c < NL_; c++) { l[c] = expf(l[c] - mx); sum += l[c]; }
        float inv = 1.0f / sum;
        #pragma unroll
        for (int c = 0; c < NL_; c++) outp[row*NL_ + c] = l[c] * inv;
    }
}

// ---------------- launch --------------------------------------------------
extern "C" void kernel_launch(void* const* d_in, const int* in_sizes, int n_in,
                              void* d_out, int out_size)
{
    const int*   ids   = (const int*)  d_in[0];
    const int*   mask  = (const int*)  d_in[1];
    const int*   types = (const int*)  d_in[2];
    const int*   valid = (const int*)  d_in[3];
    const float* we    = (const float*)d_in[4];
    const float* pe    = (const float*)d_in[5];
    const float* te    = (const float*)d_in[6];
    const float* elg   = (const float*)d_in[7];
    const float* elb   = (const float*)d_in[8];
    const float* Wq    = (const float*)d_in[9];
    const float* bq    = (const float*)d_in[10];
    const float* Wk    = (const float*)d_in[11];
    const float* bk    = (const float*)d_in[12];
    const float* Wv    = (const float*)d_in[13];
    const float* bv    = (const float*)d_in[14];
    const float* Wo    = (const float*)d_in[15];
    const float* bo    = (const float*)d_in[16];
    const float* l1g   = (const float*)d_in[17];
    const float* l1b   = (const float*)d_in[18];
    const float* Wi    = (const float*)d_in[19];
    const float* bi    = (const float*)d_in[20];
    const float* Wo2   = (const float*)d_in[21];
    const float* bo2   = (const float*)d_in[22];
    const float* l2g   = (const float*)d_in[23];
    const float* l2b   = (const float*)d_in[24];
    const float* cW    = (const float*)d_in[25];
    const float* cb    = (const float*)d_in[26];
    float* outp = (float*)d_out;

    float *ph, *pq, *pk, *pv, *pctx, *ptmp, *pff;
    cudaGetSymbolAddress((void**)&ph,   g_h);
    cudaGetSymbolAddress((void**)&pq,   g_q);
    cudaGetSymbolAddress((void**)&pk,   g_k);
    cudaGetSymbolAddress((void**)&pv,   g_v);
    cudaGetSymbolAddress((void**)&pctx, g_ctx);
    cudaGetSymbolAddress((void**)&ptmp, g_tmp);
    cudaGetSymbolAddress((void**)&pff,  g_ff);

    const int attn_smem = ATTN_SMEM_FLOATS * 4;
    cudaFuncSetAttribute(attn_fused,
                         cudaFuncAttributeMaxDynamicSharedMemorySize, attn_smem);

    const int smem64  = 2 * (64*AST  + 32*BST) * 4;   // 53,248 B
    const int smem128 = 2 * (128*AST + 32*BST) * 4;   // 71,680 B
    cudaFuncSetAttribute((const void*)gemm_cp<64,2>,
                         cudaFuncAttributeMaxDynamicSharedMemorySize, smem64);
    cudaFuncSetAttribute((const void*)gemm_cp<128,4>,
                         cudaFuncAttributeMaxDynamicSharedMemorySize, smem128);

    embed_kernel<<<M_, 256>>>(ids, types, we, pe, te, elg, elb);
    bias_kernel<<<(M_ + 255)/256, 256>>>(mask);

    dim3 gQKV(H_ / 128,  M_ / 64, 3);    // (6, 32, 3)
    dim3 gH  (H_ / 128,  M_ / 64, 1);    // (6, 32)
    dim3 gFF (FF_ / 128, M_ / 128, 1);   // (24, 16)

    for (int l = 0; l < L_; l++) {
        const float* wq = Wq + (size_t)l*H_*H_;
        const float* wk = Wk + (size_t)l*H_*H_;
        const float* wv = Wv + (size_t)l*H_*H_;
        const float* wo = Wo + (size_t)l*H_*H_;
        const float* wi = Wi + (size_t)l*H_*FF_;
        const float* w2 = Wo2 + (size_t)l*FF_*H_;

        gemm_cp<64,2><<<gQKV, 256, smem64>>>(ph, wq, wk, wv,
                                bq + l*H_, bk + l*H_, bv + l*H_,
                                pq, pk, pv, nullptr, M_, H_, H_, 0);

        attn_fused<<<dim3(S_/64, NH_, B_), 256, attn_smem>>>();

        gemm_cp<64,2><<<gH, 256, smem64>>>(pctx, wo, wo, wo,
                              bo + l*H_, bo + l*H_, bo + l*H_,
                              ptmp, ptmp, ptmp, ph, M_, H_, H_, 0);
        ln_kernel<<<M_, 256>>>(ptmp, l1g + l*H_, l1b + l*H_, ph);

        gemm_cp<128,4><<<gFF, 256, smem128>>>(ph, wi, wi, wi,
                               bi + l*FF_, bi + l*FF_, bi + l*FF_,
                               pff, pff, pff, nullptr, M_, FF_, H_, 1);
        gemm_cp<64,2><<<gH, 256, smem64>>>(pff, w2, w2, w2,
                              bo2 + l*H_, bo2 + l*H_, bo2 + l*H_,
                              ptmp, ptmp, ptmp, ph, M_, H_, FF_, 0);
        ln_kernel<<<M_, 256>>>(ptmp, l2g + l*H_, l2b + l*H_, ph);
    }

    order_kernel<<<B_, 256>>>(valid);
    compact_kernel<<<M_, 256>>>();
    clf_kernel<<<M_, 256>>>(cW, cb, outp);
}